// round 7
// baseline (speedup 1.0000x reference)
#include <cuda_runtime.h>
#include <cuda_fp16.h>
#include <cstdint>

#define N_NODES 50000
#define N_EDGES 800000
#define NGRAPHS 8
#define NCLASSES 10

typedef unsigned long long ull;

__device__ __forceinline__ void red_add_v4(float* p, float a, float b, float c, float d) {
    asm volatile("red.global.add.v4.f32 [%0], {%1, %2, %3, %4};"
                 :: "l"(p), "f"(a), "f"(b), "f"(c), "f"(d) : "memory");
}
__device__ __forceinline__ ull f32x2_fma(ull a, ull b, ull c) {
    ull d;
    asm("fma.rn.f32x2 %0, %1, %2, %3;" : "=l"(d) : "l"(a), "l"(b), "l"(c));
    return d;
}
__device__ __forceinline__ ull pack2(float x) {
    ull r;
    asm("mov.b64 %0, {%1, %1};" : "=l"(r) : "f"(x));
    return r;
}
__device__ __forceinline__ float2 unpack2(ull v) {
    float2 f;
    asm("mov.b64 {%0, %1}, %2;" : "=f"(f.x), "=f"(f.y) : "l"(v));
    return f;
}
__device__ __forceinline__ ull h2_to_ull(unsigned int h2) {
    float2 f = __half22float2(*(__half2*)&h2);
    return *(ull*)&f;
}

// ---------------- scratch (device globals) ----------------------------------------
__device__ float   g_h0  [N_NODES * 16];
__device__ float4  g_hu1 [N_NODES];        // h0 @ u1
__device__ __half2 g_xw1h[N_NODES * 64];   // h0@w1, [h*16+j] = head h, ch pair (2j,2j+1)
__device__ float   g_agg1[N_NODES * 32];
__device__ float   g_cnt [N_NODES];
__device__ float4  g_hu2 [N_NODES];        // h1 @ u2
__device__ __half2 g_xw2h[N_NODES * 128];  // h1@w2, [h*32+l] = head h, ch pair (2l,2l+1)
__device__ float   g_agg2[N_NODES * 64];
__device__ float   g_pool[NGRAPHS * 64];
__device__ float   g_gcnt[NGRAPHS];

// ---------------- zero scratch -----------------------------------------------------
__global__ void k_zero() {
    size_t idx = (size_t)blockIdx.x * blockDim.x + threadIdx.x;
    size_t stride = (size_t)gridDim.x * blockDim.x;
    for (size_t i = idx; i < (size_t)N_NODES * 64; i += stride) g_agg2[i] = 0.f;
    for (size_t i = idx; i < (size_t)N_NODES * 32; i += stride) g_agg1[i] = 0.f;
    for (size_t i = idx; i < (size_t)N_NODES;      i += stride) g_cnt[i]  = 0.f;
    if (idx < NGRAPHS * 64) g_pool[idx] = 0.f;
    if (idx < NGRAPHS)      g_gcnt[idx] = 0.f;
}

// ---------------- kernel A: h0 = relu(x@fc0+b); xw1 = h0@w1; hu1 = h0@u1 ----------
// 8 nodes per warp.
__global__ __launch_bounds__(256, 2)
void k_fc0_xw1(const float* __restrict__ x,
               const float* __restrict__ fc0_w,
               const float* __restrict__ fc0_b,
               const float* __restrict__ w1,
               const float* __restrict__ u1) {
    __shared__ float2 w1s[16 * 64];        // 8KB
    __shared__ float  u1s[64];
    const float2* w1g = (const float2*)w1;
    for (int i = threadIdx.x; i < 16 * 64; i += blockDim.x) w1s[i] = w1g[i];
    if (threadIdx.x < 64) u1s[threadIdx.x] = u1[threadIdx.x];
    __syncthreads();

    int w = threadIdx.x >> 5, lane = threadIdx.x & 31;
    int n0 = (blockIdx.x * 8 + w) * 8;
    if (n0 >= N_NODES) return;

    float hn[8];
    #pragma unroll
    for (int m = 0; m < 8; m++) {
        int n = n0 + m;
        float v = 0.f;
        if (n < N_NODES && lane < 16) {
            v = fc0_b[lane];
            #pragma unroll
            for (int j = 0; j < 3; j++) v += x[n * 3 + j] * fc0_w[j * 16 + lane];
            v = fmaxf(v, 0.f);
            g_h0[n * 16 + lane] = v;
        }
        hn[m] = v;
    }
    __syncwarp();

    // hu1[n] = h0[n] @ u1 — lanes>=16 hold 0, xor-tree over 32 lanes = exact sum.
    #pragma unroll
    for (int m = 0; m < 8; m++) {
        int n = n0 + m;
        if (n >= N_NODES) break;
        int k = lane & 15;
        float a0 = hn[m] * u1s[k * 4 + 0];
        float a1 = hn[m] * u1s[k * 4 + 1];
        float a2 = hn[m] * u1s[k * 4 + 2];
        float a3 = hn[m] * u1s[k * 4 + 3];
        #pragma unroll
        for (int off = 16; off; off >>= 1) {
            a0 += __shfl_xor_sync(0xffffffffu, a0, off);
            a1 += __shfl_xor_sync(0xffffffffu, a1, off);
            a2 += __shfl_xor_sync(0xffffffffu, a2, off);
            a3 += __shfl_xor_sync(0xffffffffu, a3, off);
        }
        if (lane == 0) g_hu1[n] = make_float4(a0, a1, a2, a3);
    }

    const ull* w1u = (const ull*)w1s;
    ull acc[8][2];
    #pragma unroll
    for (int m = 0; m < 8; m++) { acc[m][0] = 0ull; acc[m][1] = 0ull; }

    #pragma unroll
    for (int k = 0; k < 16; k++) {
        ull wk0 = w1u[k * 64 + lane];
        ull wk1 = w1u[k * 64 + 32 + lane];
        #pragma unroll
        for (int m = 0; m < 8; m++) {
            ull hk = pack2(__shfl_sync(0xffffffffu, hn[m], k));
            acc[m][0] = f32x2_fma(hk, wk0, acc[m][0]);
            acc[m][1] = f32x2_fma(hk, wk1, acc[m][1]);
        }
    }
    #pragma unroll
    for (int m = 0; m < 8; m++) {
        int n = n0 + m;
        if (n < N_NODES) {
            g_xw1h[(size_t)n * 64 + lane]      = __float22half2_rn(unpack2(acc[m][0]));
            g_xw1h[(size_t)n * 64 + 32 + lane] = __float22half2_rn(unpack2(acc[m][1]));
        }
    }
}

// ---------------- kernel B: conv1 edge pass (8 edges/warp, 4 lanes each) -----------
// Lane j (<4) covers channels 8j..8j+7 (one uint4 per head).
__global__ void k_conv1_edge(const int* __restrict__ ei,
                             const float* __restrict__ c1) {
    float cc0 = __ldg(&c1[0]), cc1 = __ldg(&c1[1]), cc2 = __ldg(&c1[2]), cc3 = __ldg(&c1[3]);
    int w = threadIdx.x >> 5, lane = threadIdx.x & 31;
    int sub = lane >> 2, j = lane & 3;
    int e = (blockIdx.x * 8 + w) * 8 + sub;
    if (e >= N_EDGES) return;

    int s = ei[e];
    int t = ei[N_EDGES + e];

    float4 a = g_hu1[s];
    float4 b = g_hu1[t];
    float l0 = a.x - b.x + cc0;
    float l1 = a.y - b.y + cc1;
    float l2 = a.z - b.z + cc2;
    float l3 = a.w - b.w + cc3;

    float m = fmaxf(fmaxf(l0, l1), fmaxf(l2, l3));
    float q0 = __expf(l0 - m), q1 = __expf(l1 - m), q2 = __expf(l2 - m), q3 = __expf(l3 - m);
    float inv = 1.f / (q0 + q1 + q2 + q3);
    float q[4] = {q0 * inv, q1 * inv, q2 * inv, q3 * inv};

    // head h: uint4 idx h*4 + j covers half2 idx h*16 + 4j..4j+3 = channels 8j..8j+7
    const uint4* xr4 = (const uint4*)(g_xw1h + (size_t)s * 64);
    ull a01 = 0ull, a23 = 0ull, a45 = 0ull, a67 = 0ull;
    #pragma unroll
    for (int h = 0; h < 4; h++) {
        uint4 p = xr4[h * 4 + j];
        ull qh = pack2(q[h]);
        a01 = f32x2_fma(qh, h2_to_ull(p.x), a01);
        a23 = f32x2_fma(qh, h2_to_ull(p.y), a23);
        a45 = f32x2_fma(qh, h2_to_ull(p.z), a45);
        a67 = f32x2_fma(qh, h2_to_ull(p.w), a67);
    }
    float2 r0 = unpack2(a01), r1 = unpack2(a23), r2 = unpack2(a45), r3 = unpack2(a67);
    red_add_v4(&g_agg1[(size_t)t * 32 + 8 * j],     r0.x, r0.y, r1.x, r1.y);
    red_add_v4(&g_agg1[(size_t)t * 32 + 8 * j + 4], r2.x, r2.y, r3.x, r3.y);
    if (j == 0) atomicAdd(&g_cnt[t], 1.0f);
}

// ---------------- kernel C: h1 epilogue + xw2 = h1@w2 + hu2 = h1@u2 (8 nodes/warp) -
__global__ __launch_bounds__(256, 2)
void k_conv1_epi_xw2(const float* __restrict__ b1,
                     const float* __restrict__ w2,
                     const float* __restrict__ u2) {
    __shared__ float2 w2s[32 * 128];       // 32KB
    __shared__ float  u2s[128];
    const float2* w2g = (const float2*)w2;
    for (int i = threadIdx.x; i < 32 * 128; i += blockDim.x) w2s[i] = w2g[i];
    if (threadIdx.x < 128) u2s[threadIdx.x] = u2[threadIdx.x];
    __syncthreads();

    int w = threadIdx.x >> 5, lane = threadIdx.x & 31;
    int n0 = (blockIdx.x * 8 + w) * 8;
    if (n0 >= N_NODES) return;

    float hn[8];
    #pragma unroll
    for (int m = 0; m < 8; m++) {
        int n = n0 + m;
        float h = 0.f;
        if (n < N_NODES) {
            float cnt = fmaxf(g_cnt[n], 1.f);
            h = fmaxf(g_agg1[(size_t)n * 32 + lane] / cnt + b1[lane], 0.f);
        }
        hn[m] = h;
    }
    __syncwarp();

    // hu2[n] = h1[n] @ u2
    #pragma unroll
    for (int m = 0; m < 8; m++) {
        int n = n0 + m;
        if (n >= N_NODES) break;
        float a0 = hn[m] * u2s[lane * 4 + 0];
        float a1 = hn[m] * u2s[lane * 4 + 1];
        float a2 = hn[m] * u2s[lane * 4 + 2];
        float a3 = hn[m] * u2s[lane * 4 + 3];
        #pragma unroll
        for (int off = 16; off; off >>= 1) {
            a0 += __shfl_xor_sync(0xffffffffu, a0, off);
            a1 += __shfl_xor_sync(0xffffffffu, a1, off);
            a2 += __shfl_xor_sync(0xffffffffu, a2, off);
            a3 += __shfl_xor_sync(0xffffffffu, a3, off);
        }
        if (lane == 0) g_hu2[n] = make_float4(a0, a1, a2, a3);
    }

    const ull* w2u = (const ull*)w2s;
    ull acc[8][4];
    #pragma unroll
    for (int m = 0; m < 8; m++)
        #pragma unroll
        for (int h = 0; h < 4; h++) acc[m][h] = 0ull;

    #pragma unroll
    for (int k = 0; k < 32; k++) {
        ull wk[4];
        #pragma unroll
        for (int h = 0; h < 4; h++) wk[h] = w2u[k * 128 + h * 32 + lane];
        #pragma unroll
        for (int m = 0; m < 8; m++) {
            ull hk = pack2(__shfl_sync(0xffffffffu, hn[m], k));
            #pragma unroll
            for (int h = 0; h < 4; h++)
                acc[m][h] = f32x2_fma(hk, wk[h], acc[m][h]);
        }
    }
    #pragma unroll
    for (int m = 0; m < 8; m++) {
        int n = n0 + m;
        if (n < N_NODES) {
            #pragma unroll
            for (int h = 0; h < 4; h++)
                g_xw2h[(size_t)n * 128 + h * 32 + lane] = __float22half2_rn(unpack2(acc[m][h]));
        }
    }
}

// ---------------- kernel D: conv2 edge pass (4 edges/warp, 8 lanes each) -----------
// Lane j (<8) covers channels 8j..8j+7 (one uint4 per head).
__global__ void k_conv2_edge(const int* __restrict__ ei,
                             const float* __restrict__ c2) {
    float cc0 = __ldg(&c2[0]), cc1 = __ldg(&c2[1]), cc2 = __ldg(&c2[2]), cc3 = __ldg(&c2[3]);
    int w = threadIdx.x >> 5, lane = threadIdx.x & 31;
    int sub = lane >> 3, j = lane & 7;
    int e = (blockIdx.x * 8 + w) * 4 + sub;
    if (e >= N_EDGES) return;

    int s = ei[e];
    int t = ei[N_EDGES + e];

    float4 a = g_hu2[s];
    float4 b = g_hu2[t];
    float l0 = a.x - b.x + cc0;
    float l1 = a.y - b.y + cc1;
    float l2 = a.z - b.z + cc2;
    float l3 = a.w - b.w + cc3;

    float m = fmaxf(fmaxf(l0, l1), fmaxf(l2, l3));
    float q0 = __expf(l0 - m), q1 = __expf(l1 - m), q2 = __expf(l2 - m), q3 = __expf(l3 - m);
    float inv = 1.f / (q0 + q1 + q2 + q3);
    float q[4] = {q0 * inv, q1 * inv, q2 * inv, q3 * inv};

    // head h: uint4 idx h*8 + j covers half2 idx h*32 + 4j..4j+3 = channels 8j..8j+7
    const uint4* xr4 = (const uint4*)(g_xw2h + (size_t)s * 128);
    ull a01 = 0ull, a23 = 0ull, a45 = 0ull, a67 = 0ull;
    #pragma unroll
    for (int h = 0; h < 4; h++) {
        uint4 p = xr4[h * 8 + j];
        ull qh = pack2(q[h]);
        a01 = f32x2_fma(qh, h2_to_ull(p.x), a01);
        a23 = f32x2_fma(qh, h2_to_ull(p.y), a23);
        a45 = f32x2_fma(qh, h2_to_ull(p.z), a45);
        a67 = f32x2_fma(qh, h2_to_ull(p.w), a67);
    }
    float2 r0 = unpack2(a01), r1 = unpack2(a23), r2 = unpack2(a45), r3 = unpack2(a67);
    red_add_v4(&g_agg2[(size_t)t * 64 + 8 * j],     r0.x, r0.y, r1.x, r1.y);
    red_add_v4(&g_agg2[(size_t)t * 64 + 8 * j + 4], r2.x, r2.y, r3.x, r3.y);
}

// ---------------- kernel E: h2 epilogue + staged global pooling --------------------
__global__ void k_conv2_epi_pool(const float* __restrict__ b2,
                                 const int* __restrict__ batch) {
    __shared__ float pools[NGRAPHS * 64];
    __shared__ float gcnts[NGRAPHS];
    for (int i = threadIdx.x; i < NGRAPHS * 64; i += blockDim.x) pools[i] = 0.f;
    if (threadIdx.x < NGRAPHS) gcnts[threadIdx.x] = 0.f;
    __syncthreads();

    int w = threadIdx.x >> 5, lane = threadIdx.x & 31;
    int n = blockIdx.x * 8 + w;
    if (n < N_NODES) {
        float cnt = fmaxf(g_cnt[n], 1.f);
        int g = batch[n];
        float h0v = fmaxf(g_agg2[(size_t)n * 64 + lane]      / cnt + b2[lane],      0.f);
        float h1v = fmaxf(g_agg2[(size_t)n * 64 + 32 + lane] / cnt + b2[32 + lane], 0.f);
        atomicAdd(&pools[g * 64 + lane],      h0v);
        atomicAdd(&pools[g * 64 + 32 + lane], h1v);
        if (lane == 0) atomicAdd(&gcnts[g], 1.f);
    }
    __syncthreads();
    for (int i = threadIdx.x; i < NGRAPHS * 64; i += blockDim.x) atomicAdd(&g_pool[i], pools[i]);
    if (threadIdx.x < NGRAPHS) atomicAdd(&g_gcnt[threadIdx.x], gcnts[threadIdx.x]);
}

// ---------------- kernel F: head ---------------------------------------------------
__global__ void k_head(const float* __restrict__ fc1_w,
                       const float* __restrict__ fc1_b,
                       float* __restrict__ out) {
    int tid = threadIdx.x;
    if (tid < NGRAPHS * NCLASSES) {
        int g = tid / NCLASSES, j = tid % NCLASSES;
        float invn = 1.f / fmaxf(g_gcnt[g], 1.f);
        float acc = 0.f;
        #pragma unroll
        for (int c = 0; c < 64; c++) acc += g_pool[g * 64 + c] * fc1_w[c * NCLASSES + j];
        out[tid] = acc * invn + fc1_b[j];
    }
}

// ---------------- launch ------------------------------------------------------------
extern "C" void kernel_launch(void* const* d_in, const int* in_sizes, int n_in,
                              void* d_out, int out_size) {
    const float* x     = (const float*)d_in[0];
    const int*   ei    = (const int*)d_in[1];
    const int*   batch = (const int*)d_in[2];
    const float* fc0_w = (const float*)d_in[3];
    const float* fc0_b = (const float*)d_in[4];
    const float* u1    = (const float*)d_in[5];
    const float* c1    = (const float*)d_in[6];
    const float* w1    = (const float*)d_in[7];
    const float* b1    = (const float*)d_in[8];
    const float* u2    = (const float*)d_in[9];
    const float* c2    = (const float*)d_in[10];
    const float* w2    = (const float*)d_in[11];
    const float* b2    = (const float*)d_in[12];
    const float* fc1_w = (const float*)d_in[13];
    const float* fc1_b = (const float*)d_in[14];
    float* out = (float*)d_out;

    k_zero<<<2048, 256>>>();
    k_fc0_xw1<<<(N_NODES + 63) / 64, 256>>>(x, fc0_w, fc0_b, w1, u1);
    k_conv1_edge<<<(N_EDGES + 63) / 64, 256>>>(ei, c1);
    k_conv1_epi_xw2<<<(N_NODES + 63) / 64, 256>>>(b1, w2, u2);
    k_conv2_edge<<<(N_EDGES + 31) / 32, 256>>>(ei, c2);
    k_conv2_epi_pool<<<(N_NODES + 7) / 8, 256>>>(b2, batch);
    k_head<<<1, 128>>>(fc1_w, fc1_b, out);
}

// round 8
// speedup vs baseline: 1.0377x; 1.0377x over previous
#include <cuda_runtime.h>
#include <cuda_fp16.h>
#include <cstdint>

#define N_NODES 50000
#define N_EDGES 800000
#define NGRAPHS 8
#define NCLASSES 10

typedef unsigned long long ull;

__device__ __forceinline__ void red_add_v4(float* p, float a, float b, float c, float d) {
    asm volatile("red.global.add.v4.f32 [%0], {%1, %2, %3, %4};"
                 :: "l"(p), "f"(a), "f"(b), "f"(c), "f"(d) : "memory");
}
__device__ __forceinline__ ull f32x2_fma(ull a, ull b, ull c) {
    ull d;
    asm("fma.rn.f32x2 %0, %1, %2, %3;" : "=l"(d) : "l"(a), "l"(b), "l"(c));
    return d;
}
__device__ __forceinline__ ull pack2(float x) {
    ull r;
    asm("mov.b64 %0, {%1, %1};" : "=l"(r) : "f"(x));
    return r;
}
__device__ __forceinline__ float2 unpack2(ull v) {
    float2 f;
    asm("mov.b64 {%0, %1}, %2;" : "=f"(f.x), "=f"(f.y) : "l"(v));
    return f;
}
__device__ __forceinline__ ull h2_to_ull(unsigned int h2) {
    float2 f = __half22float2(*(__half2*)&h2);
    return *(ull*)&f;
}

// ---------------- scratch (device globals) ----------------------------------------
// PAIR-MAJOR layout: xw[n, p, h] — half2 index p*4 + h.
//   pair p covers output channels (2p, 2p+1); heads of one pair are contiguous (16B).
__device__ float   g_h0  [N_NODES * 16];
__device__ float4  g_hu1 [N_NODES];        // h0 @ u1
__device__ __half2 g_xw1h[N_NODES * 64];   // 16 pairs x 4 heads
__device__ float   g_agg1[N_NODES * 32];
__device__ float   g_cnt [N_NODES];
__device__ float4  g_hu2 [N_NODES];        // h1 @ u2
__device__ __half2 g_xw2h[N_NODES * 128];  // 32 pairs x 4 heads
__device__ float   g_agg2[N_NODES * 64];
__device__ float   g_pool[NGRAPHS * 64];
__device__ float   g_gcnt[NGRAPHS];

// ---------------- zero scratch -----------------------------------------------------
__global__ void k_zero() {
    size_t idx = (size_t)blockIdx.x * blockDim.x + threadIdx.x;
    size_t stride = (size_t)gridDim.x * blockDim.x;
    for (size_t i = idx; i < (size_t)N_NODES * 64; i += stride) g_agg2[i] = 0.f;
    for (size_t i = idx; i < (size_t)N_NODES * 32; i += stride) g_agg1[i] = 0.f;
    for (size_t i = idx; i < (size_t)N_NODES;      i += stride) g_cnt[i]  = 0.f;
    if (idx < NGRAPHS * 64) g_pool[idx] = 0.f;
    if (idx < NGRAPHS)      g_gcnt[idx] = 0.f;
}

// ---------------- kernel A: h0 = relu(x@fc0+b); xw1 = h0@w1; hu1 = h0@u1 ----------
// 4 nodes per warp (R6 shape).
__global__ void k_fc0_xw1(const float* __restrict__ x,
                          const float* __restrict__ fc0_w,
                          const float* __restrict__ fc0_b,
                          const float* __restrict__ w1,
                          const float* __restrict__ u1) {
    __shared__ float2 w1s[16 * 64];        // 8KB
    __shared__ float  u1s[64];
    const float2* w1g = (const float2*)w1;
    for (int i = threadIdx.x; i < 16 * 64; i += blockDim.x) w1s[i] = w1g[i];
    if (threadIdx.x < 64) u1s[threadIdx.x] = u1[threadIdx.x];
    __syncthreads();

    int w = threadIdx.x >> 5, lane = threadIdx.x & 31;
    int n0 = (blockIdx.x * 8 + w) * 4;
    if (n0 >= N_NODES) return;

    float hn[4];
    #pragma unroll
    for (int m = 0; m < 4; m++) {
        int n = n0 + m;
        float v = 0.f;
        if (n < N_NODES && lane < 16) {
            v = fc0_b[lane];
            #pragma unroll
            for (int j = 0; j < 3; j++) v += x[n * 3 + j] * fc0_w[j * 16 + lane];
            v = fmaxf(v, 0.f);
            g_h0[n * 16 + lane] = v;
        }
        hn[m] = v;
    }
    __syncwarp();

    // hu1[n] = h0[n] @ u1 — lanes>=16 hold 0, xor-tree over 32 lanes = exact sum.
    #pragma unroll
    for (int m = 0; m < 4; m++) {
        int n = n0 + m;
        if (n >= N_NODES) break;
        int k = lane & 15;
        float a0 = hn[m] * u1s[k * 4 + 0];
        float a1 = hn[m] * u1s[k * 4 + 1];
        float a2 = hn[m] * u1s[k * 4 + 2];
        float a3 = hn[m] * u1s[k * 4 + 3];
        #pragma unroll
        for (int off = 16; off; off >>= 1) {
            a0 += __shfl_xor_sync(0xffffffffu, a0, off);
            a1 += __shfl_xor_sync(0xffffffffu, a1, off);
            a2 += __shfl_xor_sync(0xffffffffu, a2, off);
            a3 += __shfl_xor_sync(0xffffffffu, a3, off);
        }
        if (lane == 0) g_hu1[n] = make_float4(a0, a1, a2, a3);
    }

    const ull* w1u = (const ull*)w1s;
    ull acc[4][2];
    #pragma unroll
    for (int m = 0; m < 4; m++) { acc[m][0] = 0ull; acc[m][1] = 0ull; }

    #pragma unroll
    for (int k = 0; k < 16; k++) {
        ull wk0 = w1u[k * 64 + lane];        // flat pair i=lane     -> head lane>>4,   p=lane&15
        ull wk1 = w1u[k * 64 + 32 + lane];   // flat pair i=32+lane  -> head 2+lane>>4, p=lane&15
        #pragma unroll
        for (int m = 0; m < 4; m++) {
            ull hk = pack2(__shfl_sync(0xffffffffu, hn[m], k));
            acc[m][0] = f32x2_fma(hk, wk0, acc[m][0]);
            acc[m][1] = f32x2_fma(hk, wk1, acc[m][1]);
        }
    }
    int p = lane & 15, hh = lane >> 4;
    #pragma unroll
    for (int m = 0; m < 4; m++) {
        int n = n0 + m;
        if (n < N_NODES) {
            g_xw1h[(size_t)n * 64 + p * 4 + hh]     = __float22half2_rn(unpack2(acc[m][0]));
            g_xw1h[(size_t)n * 64 + p * 4 + 2 + hh] = __float22half2_rn(unpack2(acc[m][1]));
        }
    }
}

// ---------------- kernel B: conv1 edge pass (4 edges/warp, 8 lanes each) -----------
// Lane j (<8) covers channels 4j..4j+3 = pairs (2j, 2j+1); each pair = 1 uint4 (4 heads).
__global__ void k_conv1_edge(const int* __restrict__ ei,
                             const float* __restrict__ c1) {
    float cc0 = __ldg(&c1[0]), cc1 = __ldg(&c1[1]), cc2 = __ldg(&c1[2]), cc3 = __ldg(&c1[3]);
    int w = threadIdx.x >> 5, lane = threadIdx.x & 31;
    int sub = lane >> 3, j = lane & 7;
    int e = (blockIdx.x * 8 + w) * 4 + sub;
    if (e >= N_EDGES) return;

    int s = ei[e];
    int t = ei[N_EDGES + e];

    float4 a = g_hu1[s];
    float4 b = g_hu1[t];
    float l0 = a.x - b.x + cc0;
    float l1 = a.y - b.y + cc1;
    float l2 = a.z - b.z + cc2;
    float l3 = a.w - b.w + cc3;

    float m = fmaxf(fmaxf(l0, l1), fmaxf(l2, l3));
    float q0 = __expf(l0 - m), q1 = __expf(l1 - m), q2 = __expf(l2 - m), q3 = __expf(l3 - m);
    float inv = 1.f / (q0 + q1 + q2 + q3);
    ull qp[4] = {pack2(q0 * inv), pack2(q1 * inv), pack2(q2 * inv), pack2(q3 * inv)};

    const uint4* xr4 = (const uint4*)(g_xw1h + (size_t)s * 64);  // uint4 idx = pair p
    uint4 A = xr4[2 * j];
    uint4 B = xr4[2 * j + 1];
    ull m01 = 0ull, m23 = 0ull;
    m01 = f32x2_fma(qp[0], h2_to_ull(A.x), m01);
    m01 = f32x2_fma(qp[1], h2_to_ull(A.y), m01);
    m01 = f32x2_fma(qp[2], h2_to_ull(A.z), m01);
    m01 = f32x2_fma(qp[3], h2_to_ull(A.w), m01);
    m23 = f32x2_fma(qp[0], h2_to_ull(B.x), m23);
    m23 = f32x2_fma(qp[1], h2_to_ull(B.y), m23);
    m23 = f32x2_fma(qp[2], h2_to_ull(B.z), m23);
    m23 = f32x2_fma(qp[3], h2_to_ull(B.w), m23);
    float2 r01 = unpack2(m01), r23 = unpack2(m23);
    red_add_v4(&g_agg1[(size_t)t * 32 + 4 * j], r01.x, r01.y, r23.x, r23.y);
    if (j == 0) atomicAdd(&g_cnt[t], 1.0f);
}

// ---------------- kernel C: h1 epilogue + xw2 = h1@w2 + hu2 = h1@u2 (4 nodes/warp) -
__global__ void k_conv1_epi_xw2(const float* __restrict__ b1,
                                const float* __restrict__ w2,
                                const float* __restrict__ u2) {
    __shared__ float2 w2s[32 * 128];       // 32KB
    __shared__ float  u2s[128];
    const float2* w2g = (const float2*)w2;
    for (int i = threadIdx.x; i < 32 * 128; i += blockDim.x) w2s[i] = w2g[i];
    if (threadIdx.x < 128) u2s[threadIdx.x] = u2[threadIdx.x];
    __syncthreads();

    int w = threadIdx.x >> 5, lane = threadIdx.x & 31;
    int n0 = (blockIdx.x * 8 + w) * 4;
    if (n0 >= N_NODES) return;

    float hn[4];
    #pragma unroll
    for (int m = 0; m < 4; m++) {
        int n = n0 + m;
        float h = 0.f;
        if (n < N_NODES) {
            float cnt = fmaxf(g_cnt[n], 1.f);
            h = fmaxf(g_agg1[(size_t)n * 32 + lane] / cnt + b1[lane], 0.f);
        }
        hn[m] = h;
    }
    __syncwarp();

    // hu2[n] = h1[n] @ u2
    #pragma unroll
    for (int m = 0; m < 4; m++) {
        int n = n0 + m;
        if (n >= N_NODES) break;
        float a0 = hn[m] * u2s[lane * 4 + 0];
        float a1 = hn[m] * u2s[lane * 4 + 1];
        float a2 = hn[m] * u2s[lane * 4 + 2];
        float a3 = hn[m] * u2s[lane * 4 + 3];
        #pragma unroll
        for (int off = 16; off; off >>= 1) {
            a0 += __shfl_xor_sync(0xffffffffu, a0, off);
            a1 += __shfl_xor_sync(0xffffffffu, a1, off);
            a2 += __shfl_xor_sync(0xffffffffu, a2, off);
            a3 += __shfl_xor_sync(0xffffffffu, a3, off);
        }
        if (lane == 0) g_hu2[n] = make_float4(a0, a1, a2, a3);
    }

    const ull* w2u = (const ull*)w2s;
    ull acc[4][4];
    #pragma unroll
    for (int m = 0; m < 4; m++)
        #pragma unroll
        for (int h = 0; h < 4; h++) acc[m][h] = 0ull;

    #pragma unroll
    for (int k = 0; k < 32; k++) {
        ull wk[4];
        #pragma unroll
        for (int h = 0; h < 4; h++) wk[h] = w2u[k * 128 + h * 32 + lane];  // head h, pair p=lane
        #pragma unroll
        for (int m = 0; m < 4; m++) {
            ull hk = pack2(__shfl_sync(0xffffffffu, hn[m], k));
            #pragma unroll
            for (int h = 0; h < 4; h++)
                acc[m][h] = f32x2_fma(hk, wk[h], acc[m][h]);
        }
    }
    // pair-major store: one STG.128 per node covers pair p=lane, heads 0..3
    #pragma unroll
    for (int m = 0; m < 4; m++) {
        int n = n0 + m;
        if (n < N_NODES) {
            __half2 h0 = __float22half2_rn(unpack2(acc[m][0]));
            __half2 h1 = __float22half2_rn(unpack2(acc[m][1]));
            __half2 h2v = __float22half2_rn(unpack2(acc[m][2]));
            __half2 h3 = __float22half2_rn(unpack2(acc[m][3]));
            uint4 v = make_uint4(*(unsigned*)&h0, *(unsigned*)&h1, *(unsigned*)&h2v, *(unsigned*)&h3);
            ((uint4*)(g_xw2h + (size_t)n * 128))[lane] = v;
        }
    }
}

// ---------------- kernel D: conv2 edge pass (2 edges/warp, 16 lanes each) ----------
// Lane j (<16) covers channels 4j..4j+3 = pairs (2j, 2j+1); each pair = 1 uint4.
__global__ void k_conv2_edge(const int* __restrict__ ei,
                             const float* __restrict__ c2) {
    float cc0 = __ldg(&c2[0]), cc1 = __ldg(&c2[1]), cc2 = __ldg(&c2[2]), cc3 = __ldg(&c2[3]);
    int w = threadIdx.x >> 5, lane = threadIdx.x & 31;
    int sub = lane >> 4, j = lane & 15;
    int e = (blockIdx.x * 8 + w) * 2 + sub;
    if (e >= N_EDGES) return;

    int s = ei[e];
    int t = ei[N_EDGES + e];

    float4 a = g_hu2[s];
    float4 b = g_hu2[t];
    float l0 = a.x - b.x + cc0;
    float l1 = a.y - b.y + cc1;
    float l2 = a.z - b.z + cc2;
    float l3 = a.w - b.w + cc3;

    float m = fmaxf(fmaxf(l0, l1), fmaxf(l2, l3));
    float q0 = __expf(l0 - m), q1 = __expf(l1 - m), q2 = __expf(l2 - m), q3 = __expf(l3 - m);
    float inv = 1.f / (q0 + q1 + q2 + q3);
    ull qp[4] = {pack2(q0 * inv), pack2(q1 * inv), pack2(q2 * inv), pack2(q3 * inv)};

    const uint4* xr4 = (const uint4*)(g_xw2h + (size_t)s * 128);  // uint4 idx = pair p
    uint4 A = xr4[2 * j];
    uint4 B = xr4[2 * j + 1];
    ull m01 = 0ull, m23 = 0ull;
    m01 = f32x2_fma(qp[0], h2_to_ull(A.x), m01);
    m01 = f32x2_fma(qp[1], h2_to_ull(A.y), m01);
    m01 = f32x2_fma(qp[2], h2_to_ull(A.z), m01);
    m01 = f32x2_fma(qp[3], h2_to_ull(A.w), m01);
    m23 = f32x2_fma(qp[0], h2_to_ull(B.x), m23);
    m23 = f32x2_fma(qp[1], h2_to_ull(B.y), m23);
    m23 = f32x2_fma(qp[2], h2_to_ull(B.z), m23);
    m23 = f32x2_fma(qp[3], h2_to_ull(B.w), m23);
    float2 r01 = unpack2(m01), r23 = unpack2(m23);
    red_add_v4(&g_agg2[(size_t)t * 64 + 4 * j], r01.x, r01.y, r23.x, r23.y);
}

// ---------------- kernel E: h2 epilogue + staged global pooling --------------------
__global__ void k_conv2_epi_pool(const float* __restrict__ b2,
                                 const int* __restrict__ batch) {
    __shared__ float pools[NGRAPHS * 64];
    __shared__ float gcnts[NGRAPHS];
    for (int i = threadIdx.x; i < NGRAPHS * 64; i += blockDim.x) pools[i] = 0.f;
    if (threadIdx.x < NGRAPHS) gcnts[threadIdx.x] = 0.f;
    __syncthreads();

    int w = threadIdx.x >> 5, lane = threadIdx.x & 31;
    int n = blockIdx.x * 8 + w;
    if (n < N_NODES) {
        float cnt = fmaxf(g_cnt[n], 1.f);
        int g = batch[n];
        float h0v = fmaxf(g_agg2[(size_t)n * 64 + lane]      / cnt + b2[lane],      0.f);
        float h1v = fmaxf(g_agg2[(size_t)n * 64 + 32 + lane] / cnt + b2[32 + lane], 0.f);
        atomicAdd(&pools[g * 64 + lane],      h0v);
        atomicAdd(&pools[g * 64 + 32 + lane], h1v);
        if (lane == 0) atomicAdd(&gcnts[g], 1.f);
    }
    __syncthreads();
    for (int i = threadIdx.x; i < NGRAPHS * 64; i += blockDim.x) atomicAdd(&g_pool[i], pools[i]);
    if (threadIdx.x < NGRAPHS) atomicAdd(&g_gcnt[threadIdx.x], gcnts[threadIdx.x]);
}

// ---------------- kernel F: head ---------------------------------------------------
__global__ void k_head(const float* __restrict__ fc1_w,
                       const float* __restrict__ fc1_b,
                       float* __restrict__ out) {
    int tid = threadIdx.x;
    if (tid < NGRAPHS * NCLASSES) {
        int g = tid / NCLASSES, j = tid % NCLASSES;
        float invn = 1.f / fmaxf(g_gcnt[g], 1.f);
        float acc = 0.f;
        #pragma unroll
        for (int c = 0; c < 64; c++) acc += g_pool[g * 64 + c] * fc1_w[c * NCLASSES + j];
        out[tid] = acc * invn + fc1_b[j];
    }
}

// ---------------- launch ------------------------------------------------------------
extern "C" void kernel_launch(void* const* d_in, const int* in_sizes, int n_in,
                              void* d_out, int out_size) {
    const float* x     = (const float*)d_in[0];
    const int*   ei    = (const int*)d_in[1];
    const int*   batch = (const int*)d_in[2];
    const float* fc0_w = (const float*)d_in[3];
    const float* fc0_b = (const float*)d_in[4];
    const float* u1    = (const float*)d_in[5];
    const float* c1    = (const float*)d_in[6];
    const float* w1    = (const float*)d_in[7];
    const float* b1    = (const float*)d_in[8];
    const float* u2    = (const float*)d_in[9];
    const float* c2    = (const float*)d_in[10];
    const float* w2    = (const float*)d_in[11];
    const float* b2    = (const float*)d_in[12];
    const float* fc1_w = (const float*)d_in[13];
    const float* fc1_b = (const float*)d_in[14];
    float* out = (float*)d_out;

    k_zero<<<2048, 256>>>();
    k_fc0_xw1<<<(N_NODES + 31) / 32, 256>>>(x, fc0_w, fc0_b, w1, u1);
    k_conv1_edge<<<(N_EDGES + 31) / 32, 256>>>(ei, c1);
    k_conv1_epi_xw2<<<(N_NODES + 31) / 32, 256>>>(b1, w2, u2);
    k_conv2_edge<<<(N_EDGES + 15) / 16, 256>>>(ei, c2);
    k_conv2_epi_pool<<<(N_NODES + 7) / 8, 256>>>(b2, batch);
    k_head<<<1, 128>>>(fc1_w, fc1_b, out);
}